// round 16
// baseline (speedup 1.0000x reference)
#include <cuda_runtime.h>
#include <cuda_fp16.h>
#include <math.h>
#include <stdint.h>

#define NB 4
#define TT 2048
#define NT (NB*TT)      // 8192 tokens
#define DM 1024
#define DS 64
#define FF 2048
#define NE 8
#define NCHK 32         // TT/64 chunks per batch

#define WSCALE 64.0f
#define WINV   (1.0f/64.0f)

// ---------------- scratch (static device allocations; no cudaMalloc) --------
__device__ __half g_h1h[(size_t)NT*DM];        // compnorm1 out fp16
__device__ float  g_proj[(size_t)NT*2*DS];
__device__ float  g_states[(size_t)NT*DS];
__device__ float  g_carry[NB*NCHK*DS];
__device__ float  g_hin[NB*NCHK*DS];
__device__ float  g_x2[(size_t)NT*DM];
__device__ float  g_h2[(size_t)NT*DM];
__device__ __half g_h2h[(size_t)NT*DM];        // compnorm2 out fp16
__device__ __half g_wint[(size_t)2*128*DM];    // W_in^T fp16 hi/lo [hl][N=128][K=DM]
__device__ __half g_w1t[(size_t)NE*DM*FF];     // [e][N=FF][K=DM]
__device__ __half g_w2t[(size_t)NE*FF*DM];     // [e][N=DM][K=FF]
__device__ __half g_hidf[(size_t)NE*NT*FF];    // expert hidden fp16
__device__ __half g_obufh[(size_t)NE*NT*DM];   // expert output fp16
__device__ int    g_ecount[NE];
__device__ int    g_etok[NE*NT];
__device__ int    g_slot[NT*2];
__device__ float  g_wtok[NT*2];
__device__ float  g_partial[(NT/8)*NE];

// ---------------- PTX helpers ----------------------------------------------
__device__ __forceinline__ uint32_t smem_u32(const void* p){
    uint32_t a;
    asm("{ .reg .u64 t; cvta.to.shared.u64 t, %1; cvt.u32.u64 %0, t; }"
        : "=r"(a) : "l"(p));
    return a;
}
__device__ __forceinline__ void cp16(uint32_t d, const void* s){
    asm volatile("cp.async.cg.shared.global [%0], [%1], 16;\n" :: "r"(d), "l"(s));
}
__device__ __forceinline__ void cp_commit(){
    asm volatile("cp.async.commit_group;\n" ::: "memory");
}
template<int N> __device__ __forceinline__ void cp_wait(){
    asm volatile("cp.async.wait_group %0;\n" :: "n"(N) : "memory");
}

// fp16 HMMA: D(16x8,f32) += A(16x16,row,f16) * B(16x8,col,f16)
__device__ __forceinline__ void mma16816(float* c, const uint32_t* a, const uint32_t* b){
    asm volatile(
      "mma.sync.aligned.m16n8k16.row.col.f32.f16.f16.f32 "
      "{%0,%1,%2,%3}, {%4,%5,%6,%7}, {%8,%9}, {%0,%1,%2,%3};\n"
      : "+f"(c[0]), "+f"(c[1]), "+f"(c[2]), "+f"(c[3])
      : "r"(a[0]), "r"(a[1]), "r"(a[2]), "r"(a[3]), "r"(b[0]), "r"(b[1]));
}

__device__ __forceinline__ void ldsm_x4(uint32_t* r, uint32_t addr){
    asm volatile("ldmatrix.sync.aligned.m8n8.x4.shared.b16 {%0,%1,%2,%3}, [%4];"
      : "=r"(r[0]), "=r"(r[1]), "=r"(r[2]), "=r"(r[3]) : "r"(addr));
}

__device__ __forceinline__ uint32_t pack_half2(float a, float b){
    __half ha = __float2half_rn(a), hb = __float2half_rn(b);
    return (uint32_t)__half_as_ushort(ha) | ((uint32_t)__half_as_ushort(hb)<<16);
}

// ---------------- small kernels --------------------------------------------
__global__ void reset_kernel() {
    if (threadIdx.x < NE) g_ecount[threadIdx.x] = 0;
}

// compnorm: one block (256 thr) per row of 1024; optional fp32 out + fp16 out
__global__ void compnorm_kernel(const float* __restrict__ x,
                                const float* __restrict__ taup,
                                const float* __restrict__ scale,
                                float* __restrict__ out,
                                __half* __restrict__ oh)
{
    const int row = blockIdx.x, tid = threadIdx.x;
    const unsigned FULL = 0xffffffffu;
    float4 v = reinterpret_cast<const float4*>(x + (size_t)row*DM)[tid];
    float sq = fmaf(v.x,v.x, fmaf(v.y,v.y, fmaf(v.z,v.z, v.w*v.w)));
    float mx = fmaxf(fmaxf(v.x,v.y), fmaxf(v.z,v.w));
    __shared__ float rq[8], rm[8], rz[8];
    #pragma unroll
    for (int o=16;o;o>>=1){
        sq += __shfl_xor_sync(FULL,sq,o);
        mx  = fmaxf(mx, __shfl_xor_sync(FULL,mx,o));
    }
    int w = tid>>5, lane = tid&31;
    if (!lane){ rq[w]=sq; rm[w]=mx; }
    __syncthreads();
    float Q=0.f, MX=-3.4e38f;
    #pragma unroll
    for (int i=0;i<8;i++){ Q+=rq[i]; MX=fmaxf(MX,rm[i]); }
    const float it = 1.0f / fmaxf(taup[0], 1.0f);
    float4 g;
    g.x = expf((v.x-MX)*it); g.y = expf((v.y-MX)*it);
    g.z = expf((v.z-MX)*it); g.w = expf((v.w-MX)*it);
    float z = g.x+g.y+g.z+g.w;
    #pragma unroll
    for (int o=16;o;o>>=1) z += __shfl_xor_sync(FULL,z,o);
    if (!lane) rz[w]=z;
    __syncthreads();
    float Z=0.f;
    #pragma unroll
    for (int i=0;i<8;i++) Z += rz[i];
    const float rms = rsqrtf(Q*(1.0f/DM) + 1e-8f);
    const float c = rms * (float)DM / Z;
    float4 sc = reinterpret_cast<const float4*>(scale)[tid];
    float4 o4;
    o4.x = v.x*g.x*c*sc.x; o4.y = v.y*g.y*c*sc.y;
    o4.z = v.z*g.z*c*sc.z; o4.w = v.w*g.w*c*sc.w;
    if (out)
        reinterpret_cast<float4*>(out + (size_t)row*DM)[tid] = o4;
    uint2 hp;
    hp.x = pack_half2(o4.x, o4.y);
    hp.y = pack_half2(o4.z, o4.w);
    *reinterpret_cast<uint2*>(oh + (size_t)row*DM + tid*4) = hp;
}

// transpose: W [K,N] fp32 per expert -> out [e][N][K] fp16 (x64).
// If lo_out != nullptr, also writes the fp16 residual (2-term split).
__global__ void convT_kernel(const float* __restrict__ W,
                             __half* __restrict__ out,
                             __half* __restrict__ lo_out, int K, int N)
{
    __shared__ float t[32][33];
    int e = blockIdx.z;
    const float* Wp = W + (size_t)e*K*N;
    __half* hi = out + (size_t)e*(size_t)K*N;
    int k0 = blockIdx.x*32, n0 = blockIdx.y*32;
    int tx = threadIdx.x, ty = threadIdx.y;
    #pragma unroll
    for (int i=0;i<4;i++)
        t[ty+i*8][tx] = Wp[(size_t)(k0+ty+i*8)*N + n0+tx];
    __syncthreads();
    #pragma unroll
    for (int i=0;i<4;i++){
        float v = t[tx][ty+i*8] * WSCALE;
        __half h = __float2half_rn(v);
        size_t o = (size_t)(n0+ty+i*8)*K + k0+tx;
        hi[o] = h;
        if (lo_out)
            lo_out[(size_t)e*(size_t)K*N + o] = __float2half_rn(v - __half2float(h));
    }
}

// ---- parallel LRU scan, phase 1: per-chunk local scan (u fused from proj) --
__global__ void scan_local_kernel(const float* __restrict__ rec_w,
                                  const float* __restrict__ pos_bias)
{
    const int idx = blockIdx.x;            // (b, chunk): 0..127
    const int b = idx >> 5, c = idx & 31;
    const int d = threadIdx.x;             // 64 threads
    const float a = 1.0f / (1.0f + expf(-(rec_w[d] + pos_bias[d])));
    const size_t base = (size_t)b*TT + (size_t)c*64;
    float l = 0.f;
    #pragma unroll 8
    for (int t=0; t<64; t++){
        size_t row = base + t;
        float vin = tanhf(g_proj[row*2*DS + d]);
        float vg  = 1.0f / (1.0f + expf(-g_proj[row*2*DS + DS + d]));
        l = fmaf(a, l, vin*vg);
        g_states[row*DS + d] = l;
    }
    g_carry[idx*DS + d] = l;
}

// ---- phase 2: serial carry across chunks (32 steps, L2-resident) ----------
__global__ void scan_carry_kernel(const float* __restrict__ state,
                                  const float* __restrict__ rec_w,
                                  const float* __restrict__ pos_bias,
                                  float* __restrict__ out_state)
{
    const int tid = threadIdx.x;           // 256: (b,d)
    const int b = tid >> 6, d = tid & 63;
    const float a = 1.0f / (1.0f + expf(-(rec_w[d] + pos_bias[d])));
    float aC = a;
    #pragma unroll
    for (int i=0;i<6;i++) aC *= aC;        // a^64
    float h = state[tid];
    #pragma unroll
    for (int c=0; c<NCHK; c++){
        int o = (b*NCHK + c)*DS + d;
        g_hin[o] = h;
        h = fmaf(aC, h, g_carry[o]);
    }
    out_state[tid] = h;
}

// ---- phase 3: fixup locals with carry-in ----------------------------------
__global__ void scan_fix_kernel(const float* __restrict__ rec_w,
                                const float* __restrict__ pos_bias)
{
    const int idx = blockIdx.x;            // 0..127
    const int b = idx >> 5, c = idx & 31;
    const int d = threadIdx.x;
    const float a = 1.0f / (1.0f + expf(-(rec_w[d] + pos_bias[d])));
    const float hin = g_hin[idx*DS + d];
    const size_t base = ((size_t)b*TT + (size_t)c*64)*DS + d;
    float p = a;
    #pragma unroll 8
    for (int t=0; t<64; t++){
        g_states[base + (size_t)t*DS] = fmaf(p, hin, g_states[base + (size_t)t*DS]);
        p *= a;
    }
}

__global__ void router_kernel(const float* __restrict__ Wr,
                              const float* __restrict__ h2)
{
    int warp = threadIdx.x >> 5, lane = threadIdx.x & 31;
    int token = blockIdx.x*8 + warp;
    const unsigned FULL = 0xffffffffu;
    const float* xr = h2 + (size_t)token*DM;
    float acc[NE];
    #pragma unroll
    for (int e=0;e<NE;e++) acc[e]=0.f;
    for (int k=lane;k<DM;k+=32){
        float xv = xr[k];
        const float* wrow = Wr + k*NE;
        #pragma unroll
        for (int e=0;e<NE;e++) acc[e] = fmaf(xv, wrow[e], acc[e]);
    }
    #pragma unroll
    for (int o=16;o;o>>=1)
        #pragma unroll
        for (int e=0;e<NE;e++) acc[e] += __shfl_xor_sync(FULL, acc[e], o);

    __shared__ float sp[8][NE];
    if (lane==0){
        float mxv = acc[0];
        #pragma unroll
        for (int e=1;e<NE;e++) mxv = fmaxf(mxv, acc[e]);
        float p[NE]; float s=0.f;
        #pragma unroll
        for (int e=0;e<NE;e++){ p[e] = expf(acc[e]-mxv); s += p[e]; }
        float inv = 1.0f/s;
        #pragma unroll
        for (int e=0;e<NE;e++) p[e] *= inv;
        int i0=0; float p0=p[0];
        #pragma unroll
        for (int e=1;e<NE;e++) if (p[e] > p0){ p0=p[e]; i0=e; }
        int i1=-1; float p1=-1.f;
        #pragma unroll
        for (int e=0;e<NE;e++) if (e!=i0 && p[e] > p1){ p1=p[e]; i1=e; }
        float ws = 1.0f/(p0+p1);
        g_wtok[token*2+0] = p0*ws;
        g_wtok[token*2+1] = p1*ws;
        int pos0 = atomicAdd(&g_ecount[i0], 1);
        g_etok[i0*NT + pos0] = token;
        g_slot[token*2+0] = i0*NT + pos0;
        int pos1 = atomicAdd(&g_ecount[i1], 1);
        g_etok[i1*NT + pos1] = token;
        g_slot[token*2+1] = i1*NT + pos1;
        #pragma unroll
        for (int e=0;e<NE;e++) sp[warp][e] = p[e];
    }
    __syncthreads();
    if (threadIdx.x < NE){
        float s=0.f;
        #pragma unroll
        for (int w2=0;w2<8;w2++) s += sp[w2][threadIdx.x];
        g_partial[blockIdx.x*NE + threadIdx.x] = s;
    }
}

__global__ void aux_kernel(float* __restrict__ out)
{
    const unsigned FULL = 0xffffffffu;
    int e = threadIdx.x;
    float val = 0.f;
    if (e < NE){
        float s = 0.f;
        for (int b=0;b<NT/8;b++) s += g_partial[b*NE + e];
        float P = s / (float)NT;
        float f = (float)g_ecount[e] / (float)(NT*2);
        val = f * P;
    }
    #pragma unroll
    for (int o=16;o;o>>=1) val += __shfl_xor_sync(FULL, val, o);
    if (threadIdx.x==0) out[0] = (float)NE * val;
}

__global__ void combine_kernel(const float* __restrict__ x2,
                               float* __restrict__ out)
{
    int n = blockIdx.x, tid = threadIdx.x;
    int s0 = g_slot[n*2+0], s1 = g_slot[n*2+1];
    float w0 = g_wtok[n*2+0], w1 = g_wtok[n*2+1];
    float4 a = reinterpret_cast<const float4*>(x2 + (size_t)n*DM)[tid];
    uint2 pu = *reinterpret_cast<const uint2*>(g_obufh + (size_t)s0*DM + tid*4);
    uint2 qu = *reinterpret_cast<const uint2*>(g_obufh + (size_t)s1*DM + tid*4);
    float2 p0 = __half22float2(*reinterpret_cast<__half2*>(&pu.x));
    float2 p1 = __half22float2(*reinterpret_cast<__half2*>(&pu.y));
    float2 q0 = __half22float2(*reinterpret_cast<__half2*>(&qu.x));
    float2 q1 = __half22float2(*reinterpret_cast<__half2*>(&qu.y));
    a.x += fmaf(w1, q0.x, w0*p0.x);
    a.y += fmaf(w1, q0.y, w0*p0.y);
    a.z += fmaf(w1, q1.x, w0*p1.x);
    a.w += fmaf(w1, q1.y, w0*p1.y);
    reinterpret_cast<float4*>(out + (size_t)n*DM)[tid] = a;
}

// ---------------- fp32 SIMT GEMM (W_out only: K=64) -------------------------
template<int MODE>
__global__ void __launch_bounds__(256)
gemm128_kernel(const float* __restrict__ A, int lda,
               const float* __restrict__ Bm, int ldb,
               const float* __restrict__ bias,
               float* __restrict__ C, int ldc,
               int M, int K,
               const float* __restrict__ resid)
{
    const int m0 = blockIdx.y * 128;
    const int n0 = blockIdx.x * 128;

    __shared__ __align__(16) float As[8][128];
    __shared__ __align__(16) float Bs[8][128];

    const int tid = threadIdx.x;
    const int arow_l = tid >> 1;
    const int kpart  = (tid & 1) * 4;
    const int arow   = m0 + arow_l;
    const float* aptr = (arow < M) ? A + (size_t)arow*lda + kpart : A + kpart;

    const int bk = tid >> 5;
    const int bn = (tid & 31) * 4;
    const float* bptr = Bm + (size_t)bk*ldb + n0 + bn;

    const int ty = tid >> 4;
    const int tx = tid & 15;

    float acc[8][8];
    #pragma unroll
    for (int i=0;i<8;i++)
        #pragma unroll
        for (int j=0;j<8;j++) acc[i][j]=0.f;

    for (int k0=0; k0<K; k0+=8){
        float4 av = *reinterpret_cast<const float4*>(aptr + k0);
        float4 bv = *reinterpret_cast<const float4*>(bptr + (size_t)k0*ldb);
        As[kpart+0][arow_l] = av.x;
        As[kpart+1][arow_l] = av.y;
        As[kpart+2][arow_l] = av.z;
        As[kpart+3][arow_l] = av.w;
        *reinterpret_cast<float4*>(&Bs[bk][bn]) = bv;
        __syncthreads();
        #pragma unroll
        for (int k=0;k<8;k++){
            float4 a0 = *reinterpret_cast<const float4*>(&As[k][ty*8]);
            float4 a1 = *reinterpret_cast<const float4*>(&As[k][ty*8+4]);
            float4 b0 = *reinterpret_cast<const float4*>(&Bs[k][tx*8]);
            float4 b1 = *reinterpret_cast<const float4*>(&Bs[k][tx*8+4]);
            float am[8] = {a0.x,a0.y,a0.z,a0.w,a1.x,a1.y,a1.z,a1.w};
            float bb[8] = {b0.x,b0.y,b0.z,b0.w,b1.x,b1.y,b1.z,b1.w};
            #pragma unroll
            for (int i=0;i<8;i++)
                #pragma unroll
                for (int j=0;j<8;j++)
                    acc[i][j] = fmaf(am[i], bb[j], acc[i][j]);
        }
        __syncthreads();
    }

    #pragma unroll
    for (int i=0;i<8;i++){
        int r = m0 + ty*8 + i;
        if (r < M){
            float v[8];
            #pragma unroll
            for (int j=0;j<8;j++) v[j] = acc[i][j] + bias[n0 + tx*8 + j];
            if (MODE==2){
                const float4* rp = reinterpret_cast<const float4*>(
                    resid + (size_t)r*ldc + n0 + tx*8);
                float4 r0 = rp[0], r1 = rp[1];
                v[0]+=r0.x; v[1]+=r0.y; v[2]+=r0.z; v[3]+=r0.w;
                v[4]+=r1.x; v[5]+=r1.y; v[6]+=r1.z; v[7]+=r1.w;
            }
            float4* cp = reinterpret_cast<float4*>(C + (size_t)r*ldc + n0 + tx*8);
            cp[0] = make_float4(v[0],v[1],v[2],v[3]);
            cp[1] = make_float4(v[4],v[5],v[6],v[7]);
        }
    }
}

// ---------------- mma.sync fp16 GEMM (templated N-tile) ---------------------
// 4-stage cp.async pipeline, ONE __syncthreads per K-chunk, ldmatrix x4 frags.
// C[128,NTILE] = (1/64)*( A@Bh^T [+ A@Bl^T] ) + bias  (B fp16 pre-scaled x64)
// MODE 0: fp32 out.  MODE 1: silu -> fp16 out.  MODE 2: plain fp16 out.
// GATHER: A rows via g_etok.  EXPERT: blockIdx.z = expert.
static constexpr int ROWB = 80;                    // 32 halves (64B) + 16 pad
static constexpr int ATILEB = 128*ROWB;            // 10240
static constexpr int NST = 4;                      // pipeline stages

template<int KSTRIDE, int NTILE, int BTERMS, int MODE, bool GATHER, bool EXPERT>
__global__ void __launch_bounds__(256, (NTILE==128) ? 2 : 1)
mmagemm_kernel(const __half* __restrict__ Ain,
               const __half* __restrict__ Wt, int Ntot,
               const float* __restrict__ bias, int biasStride,
               float* __restrict__ Cf,
               __half* __restrict__ Ch,
               int ldc, int Min)
{
    constexpr int BTILEB = NTILE*ROWB;
    constexpr int BHo = ATILEB;
    constexpr int BLo = ATILEB + BTILEB;
    constexpr int SB = ATILEB + BTERMS*BTILEB;     // per-stage smem bytes
    constexpr int NWT = NTILE/16;                  // nt tiles per warp
    const int e = EXPERT ? blockIdx.z : 0;
    const int M = EXPERT ? g_ecount[e] : Min;
    const int m0 = blockIdx.y * 128;
    if (m0 >= M) return;
    const int n0 = blockIdx.x * NTILE;

    const __half* A = Ain;
    const __half* Bp = Wt + (EXPERT ? (size_t)e*(size_t)Ntot*KSTRIDE : (size_t)0);
    const __half* Bl = Bp + (size_t)Ntot*KSTRIDE;  // 2-term: lo plane follows hi

    extern __shared__ char sm[];
    __shared__ int   s_tok[128];
    __shared__ float s_bias[NTILE];

    const int tid = threadIdx.x;
    const int lane = tid & 31, wid = tid >> 5;
    const int warp_m = wid & 3, warp_n = wid >> 2;   // 4 x 2 warps

    if (GATHER && tid < 128){
        int r = m0 + tid;
        s_tok[tid] = (r < M) ? g_etok[e*NT + r] : g_etok[e*NT];
    }
    #pragma unroll
    for (int i = tid; i < NTILE; i += 256)
        s_bias[i] = bias[(size_t)e*biasStride + n0 + i];
    __syncthreads();

    const size_t rowBase = (EXPERT ? (size_t)e*NT : (size_t)0) + m0;
    const uint32_t smb = smem_u32(sm);

    auto load_chunk = [&](int c, int s){
        const int k0 = c*32;
        const uint32_t st = smb + (uint32_t)s*SB;
        #pragma unroll
        for (int i = tid; i < 512; i += 256){
            int row = i >> 2, sg = i & 3;
            size_t ar = GATHER ? (size_t)s_tok[row] : (rowBase + row);
            size_t so = ar*(size_t)KSTRIDE + k0 + sg*8;
            uint32_t d = (uint32_t)(row*ROWB + sg*16);
            cp16(st + d, A + so);
        }
        #pragma unroll
        for (int i = tid; i < NTILE*4; i += 256){
            int row = i >> 2, sg = i & 3;
            size_t so = (size_t)(n0+row)*KSTRIDE + k0 + sg*8;
            uint32_t d = (uint32_t)(row*ROWB + sg*16);
            cp16(st + BHo + d, Bp + so);
            if (BTERMS == 2)
                cp16(st + BLo + d, Bl + so);
        }
        cp_commit();
    };

    float acc[2][NWT][4];
    #pragma unroll
    for (int i=0;i<2;i++)
        #pragma unroll
        for (int j=0;j<NWT;j++)
            #pragma unroll
            for (int q=0;q<4;q++) acc[i][j][q]=0.f;

    const int NCH = KSTRIDE/32;                    // >= 32 always
    load_chunk(0,0);
    load_chunk(1,1);
    load_chunk(2,2);

    // ldmatrix per-thread selectors
    const int rA = lane & 15;                      // A: rows 0-15 of the 16x16 frag
    const uint32_t cA = (uint32_t)(lane >> 4) * 16;// lanes>=16: k+8 (16B)
    // B x4: matrix id = lane>>3: m0=(nt,k0) m1=(nt,k8) m2=(nt+1,k0) m3=(nt+1,k8)
    const int rB = lane & 7;
    const uint32_t nB = (uint32_t)((lane >> 4) & 1) * 8;   // +8 n-rows for m2/m3
    const uint32_t cB = (uint32_t)((lane >> 3) & 1) * 16;  // k8 half for m1/m3

    for (int c = 0; c < NCH; c++){
        const int rem = NCH - 1 - c;               // loads issued after chunk c
        if (rem >= 2)      cp_wait<2>();
        else if (rem == 1) cp_wait<1>();
        else               cp_wait<0>();
        __syncthreads();                           // single barrier per chunk
        const uint32_t S = smb + (uint32_t)(c & 3)*SB;

        #pragma unroll
        for (int ks = 0; ks < 2; ks++){
            const uint32_t kbase = (uint32_t)ks*32;
            uint32_t ah[2][4];
            #pragma unroll
            for (int mt=0; mt<2; mt++){
                uint32_t addr = S
                    + (uint32_t)((warp_m*32 + mt*16 + rA)*ROWB) + kbase + cA;
                ldsm_x4(ah[mt], addr);
            }
            #pragma unroll
            for (int nt=0; nt<NWT; nt+=2){
                const uint32_t nrow =
                    (uint32_t)((warp_n*(NTILE/2) + nt*8 + nB + rB)*ROWB);
                uint32_t bb[4];
                ldsm_x4(bb, S + BHo + nrow + kbase + cB);
                #pragma unroll
                for (int mt=0; mt<2; mt++){
                    mma16816(acc[mt][nt],   ah[mt], &bb[0]);
                    mma16816(acc[mt][nt+1], ah[mt], &bb[2]);
                }
                if (BTERMS == 2){
                    uint32_t bl[4];
                    ldsm_x4(bl, S + BLo + nrow + kbase + cB);
                    #pragma unroll
                    for (int mt=0; mt<2; mt++){
                        mma16816(acc[mt][nt],   ah[mt], &bl[0]);
                        mma16816(acc[mt][nt+1], ah[mt], &bl[2]);
                    }
                }
            }
        }
        // load 3 ahead into stage (c+3)&3 — its last readers ran chunk c-1,
        // which every warp finished before this chunk's barrier.
        if (c+3 < NCH) load_chunk(c+3, (c+3) & 3);
    }

    // ---- epilogue ----
    const int colb = warp_n*(NTILE/2) + (lane&3)*2;
    #pragma unroll
    for (int mt=0; mt<2; mt++){
        int rl = m0 + warp_m*32 + mt*16 + (lane>>2);   // rows rl, rl+8
        #pragma unroll
        for (int nt=0; nt<NWT; nt++){
            int ncol = colb + nt*8;
            float b0 = s_bias[ncol], b1 = s_bias[ncol+1];
            float v0 = fmaf(acc[mt][nt][0], WINV, b0);
            float v1 = fmaf(acc[mt][nt][1], WINV, b1);
            float v2 = fmaf(acc[mt][nt][2], WINV, b0);
            float v3 = fmaf(acc[mt][nt][3], WINV, b1);
            if (MODE != 0){
                if (MODE == 1){
                    v0 = v0/(1.0f+expf(-v0)); v1 = v1/(1.0f+expf(-v1));
                    v2 = v2/(1.0f+expf(-v2)); v3 = v3/(1.0f+expf(-v3));
                }
                if (rl < M){
                    size_t off = (rowBase - m0 + rl)*(size_t)ldc + n0 + ncol;
                    *reinterpret_cast<uint32_t*>(Ch + off) = pack_half2(v0, v1);
                }
                if (rl + 8 < M){
                    size_t off = (rowBase - m0 + rl + 8)*(size_t)ldc + n0 + ncol;
                    *reinterpret_cast<uint32_t*>(Ch + off) = pack_half2(v2, v3);
                }
            } else {
                if (rl < M){
                    size_t off = (rowBase - m0 + rl)*(size_t)ldc + n0 + ncol;
                    *reinterpret_cast<float2*>(Cf + off) = make_float2(v0, v1);
                }
                if (rl + 8 < M){
                    size_t off = (rowBase - m0 + rl + 8)*(size_t)ldc + n0 + ncol;
                    *reinterpret_cast<float2*>(Cf + off) = make_float2(v2, v3);
                }
            }
        }
    }
}

static constexpr int MM_DYN_E = NST*(ATILEB + 256*ROWB);    // experts: 122880
static constexpr int MM_DYN_P = NST*(ATILEB + 2*128*ROWB);  // proj 2-term: 122880

// ---------------- launch ----------------------------------------------------
extern "C" void kernel_launch(void* const* d_in, const int* in_sizes, int n_in,
                              void* d_out, int out_size)
{
    const float* x      = (const float*)d_in[0];
    const float* state  = (const float*)d_in[1];
    const float* tau1   = (const float*)d_in[2];
    const float* scale1 = (const float*)d_in[3];
    const float* tau2   = (const float*)d_in[4];
    const float* scale2 = (const float*)d_in[5];
    const float* W_in   = (const float*)d_in[6];
    const float* b_in   = (const float*)d_in[7];
    const float* rec_w  = (const float*)d_in[8];
    const float* pos_b  = (const float*)d_in[9];
    const float* W_out  = (const float*)d_in[10];
    const float* b_out  = (const float*)d_in[11];
    const float* W_r    = (const float*)d_in[12];
    const float* We1    = (const float*)d_in[13];
    const float* be1    = (const float*)d_in[14];
    const float* We2    = (const float*)d_in[15];
    const float* be2    = (const float*)d_in[16];
    float* out = (float*)d_out;
    float* out_state = out + (size_t)NT*DM;
    float* out_aux   = out_state + NB*DS;

    float *p_proj, *p_states, *p_x2, *p_h2;
    __half *p_h1h, *p_h2h, *p_wint, *p_w1t, *p_w2t, *p_hidf, *p_obufh;
    cudaGetSymbolAddress((void**)&p_h1h,   g_h1h);
    cudaGetSymbolAddress((void**)&p_proj,  g_proj);
    cudaGetSymbolAddress((void**)&p_states,g_states);
    cudaGetSymbolAddress((void**)&p_x2,    g_x2);
    cudaGetSymbolAddress((void**)&p_h2,    g_h2);
    cudaGetSymbolAddress((void**)&p_h2h,   g_h2h);
    cudaGetSymbolAddress((void**)&p_wint,  g_wint);
    cudaGetSymbolAddress((void**)&p_w1t,   g_w1t);
    cudaGetSymbolAddress((void**)&p_w2t,   g_w2t);
    cudaGetSymbolAddress((void**)&p_hidf,  g_hidf);
    cudaGetSymbolAddress((void**)&p_obufh, g_obufh);

    cudaFuncSetAttribute(mmagemm_kernel<DM, 128, 2, 0, false, false>,
                         cudaFuncAttributeMaxDynamicSharedMemorySize, MM_DYN_P);
    cudaFuncSetAttribute(mmagemm_kernel<DM, 256, 1, 1, true, true>,
                         cudaFuncAttributeMaxDynamicSharedMemorySize, MM_DYN_E);
    cudaFuncSetAttribute(mmagemm_kernel<FF, 256, 1, 2, false, true>,
                         cudaFuncAttributeMaxDynamicSharedMemorySize, MM_DYN_E);

    // side stream + events for weight-prep overlap (created once, uncaptured run)
    static cudaStream_t s2 = nullptr;
    static cudaEvent_t evFork = nullptr, evJoin = nullptr;
    if (!s2){
        cudaStreamCreateWithFlags(&s2, cudaStreamNonBlocking);
        cudaEventCreateWithFlags(&evFork, cudaEventDisableTiming);
        cudaEventCreateWithFlags(&evJoin, cudaEventDisableTiming);
    }

    reset_kernel<<<1,32>>>();

    // fork: expert weight transposes run concurrently with the LRU chain
    cudaEventRecord(evFork, 0);
    cudaStreamWaitEvent(s2, evFork, 0);
    convT_kernel<<<dim3(DM/32, FF/32, NE), dim3(32,8), 0, s2>>>(We1, p_w1t, nullptr, DM, FF);
    convT_kernel<<<dim3(FF/32, DM/32, NE), dim3(32,8), 0, s2>>>(We2, p_w2t, nullptr, FF, DM);
    cudaEventRecord(evJoin, s2);

    // main chain: W_in transpose (needed by proj) stays here
    convT_kernel<<<dim3(DM/32, 128/32, 1), dim3(32,8)>>>(
        W_in, p_wint, p_wint + (size_t)128*DM, DM, 128);

    // 1. compnorm1 (fp16 only)
    compnorm_kernel<<<NT,256>>>(x, tau1, scale1, nullptr, p_h1h);

    // 2. proj = h1 @ W_in + b_in  (mma, N=128, 2-term B: router-path accuracy)
    mmagemm_kernel<DM, 128, 2, 0, false, false><<<dim3(1, NT/128), 256, MM_DYN_P>>>(
        p_h1h, p_wint, 128, b_in, 0, p_proj, nullptr, 128, NT);

    // 3-4. parallel LRU scan (u fused from proj)
    scan_local_kernel<<<NB*NCHK, 64>>>(rec_w, pos_b);
    scan_carry_kernel<<<1, 256>>>(state, rec_w, pos_b, out_state);
    scan_fix_kernel<<<NB*NCHK, 64>>>(rec_w, pos_b);

    // 5. x2 = x + states @ W_out + b_out  (SIMT fp32, K=64)
    gemm128_kernel<2><<<dim3(DM/128, NT/128), 256>>>(
        p_states, DS, W_out, DM, b_out, p_x2, DM, NT, DS, x);

    // 6. compnorm2 (fp32 for router + fp16 for mma)
    compnorm_kernel<<<NT,256>>>(p_x2, tau2, scale2, p_h2, p_h2h);

    // 7. router + dispatch
    router_kernel<<<NT/8, 256>>>(W_r, p_h2);

    // 8. aux loss
    aux_kernel<<<1,32>>>(out_aux);

    // join: expert weights must be ready before GEMM1
    cudaStreamWaitEvent(0, evJoin, 0);

    // 9. expert GEMM1: hidden = silu(gather(h2) @ We1[e] + be1[e]) -> fp16
    mmagemm_kernel<DM, 256, 1, 1, true, true><<<dim3(FF/256, NT/128, NE), 256, MM_DYN_E>>>(
        p_h2h, p_w1t, FF, be1, FF, nullptr, p_hidf, FF, 0);

    // 10. expert GEMM2: obuf = hidden @ We2[e] + be2[e] -> fp16
    mmagemm_kernel<FF, 256, 1, 2, false, true><<<dim3(DM/256, NT/128, NE), 256, MM_DYN_E>>>(
        p_hidf, p_w2t, DM, be2, DM, nullptr, p_obufh, DM, 0);

    // 11. combine into d_out
    combine_kernel<<<NT,256>>>(p_x2, out);
}

// round 17
// speedup vs baseline: 1.1576x; 1.1576x over previous
#include <cuda_runtime.h>
#include <cuda_fp16.h>
#include <math.h>
#include <stdint.h>

#define NB 4
#define TT 2048
#define NT (NB*TT)      // 8192 tokens
#define DM 1024
#define DS 64
#define FF 2048
#define NE 8
#define NCHK 32         // TT/64 chunks per batch

#define WSCALE 64.0f
#define WINV   (1.0f/64.0f)

// ---------------- scratch (static device allocations; no cudaMalloc) --------
__device__ __half g_h1h[(size_t)NT*DM];        // compnorm1 out fp16
__device__ float  g_proj[(size_t)NT*2*DS];
__device__ float  g_states[(size_t)NT*DS];
__device__ float  g_carry[NB*NCHK*DS];
__device__ float  g_hin[NB*NCHK*DS];
__device__ float  g_x2[(size_t)NT*DM];
__device__ float  g_h2[(size_t)NT*DM];
__device__ __half g_h2h[(size_t)NT*DM];        // compnorm2 out fp16
__device__ __half g_wint[(size_t)2*128*DM];    // W_in^T fp16 hi/lo [hl][N=128][K=DM]
__device__ __half g_w1t[(size_t)NE*DM*FF];     // [e][N=FF][K=DM]
__device__ __half g_w2t[(size_t)NE*FF*DM];     // [e][N=DM][K=FF]
__device__ __half g_hidf[(size_t)NE*NT*FF];    // expert hidden fp16
__device__ __half g_obufh[(size_t)NE*NT*DM];   // expert output fp16
__device__ int    g_ecount[NE];
__device__ int    g_etok[NE*NT];
__device__ int    g_slot[NT*2];
__device__ float  g_wtok[NT*2];
__device__ float  g_partial[(NT/8)*NE];

// ---------------- PTX helpers ----------------------------------------------
__device__ __forceinline__ uint32_t smem_u32(const void* p){
    uint32_t a;
    asm("{ .reg .u64 t; cvta.to.shared.u64 t, %1; cvt.u32.u64 %0, t; }"
        : "=r"(a) : "l"(p));
    return a;
}
__device__ __forceinline__ void cp16(uint32_t d, const void* s){
    asm volatile("cp.async.cg.shared.global [%0], [%1], 16;\n" :: "r"(d), "l"(s));
}
__device__ __forceinline__ void cp_commit(){
    asm volatile("cp.async.commit_group;\n" ::: "memory");
}
template<int N> __device__ __forceinline__ void cp_wait(){
    asm volatile("cp.async.wait_group %0;\n" :: "n"(N) : "memory");
}

// fp16 HMMA: D(16x8,f32) += A(16x16,row,f16) * B(16x8,col,f16)
__device__ __forceinline__ void mma16816(float* c, const uint32_t* a, const uint32_t* b){
    asm volatile(
      "mma.sync.aligned.m16n8k16.row.col.f32.f16.f16.f32 "
      "{%0,%1,%2,%3}, {%4,%5,%6,%7}, {%8,%9}, {%0,%1,%2,%3};\n"
      : "+f"(c[0]), "+f"(c[1]), "+f"(c[2]), "+f"(c[3])
      : "r"(a[0]), "r"(a[1]), "r"(a[2]), "r"(a[3]), "r"(b[0]), "r"(b[1]));
}

__device__ __forceinline__ void ldsm_x4(uint32_t* r, uint32_t addr){
    asm volatile("ldmatrix.sync.aligned.m8n8.x4.shared.b16 {%0,%1,%2,%3}, [%4];"
      : "=r"(r[0]), "=r"(r[1]), "=r"(r[2]), "=r"(r[3]) : "r"(addr));
}

__device__ __forceinline__ uint32_t pack_half2(float a, float b){
    __half ha = __float2half_rn(a), hb = __float2half_rn(b);
    return (uint32_t)__half_as_ushort(ha) | ((uint32_t)__half_as_ushort(hb)<<16);
}

// ---------------- small kernels --------------------------------------------
__global__ void reset_kernel() {
    if (threadIdx.x < NE) g_ecount[threadIdx.x] = 0;
}

// compnorm: one block (256 thr) per row of 1024; optional fp32 out + fp16 out
__global__ void compnorm_kernel(const float* __restrict__ x,
                                const float* __restrict__ taup,
                                const float* __restrict__ scale,
                                float* __restrict__ out,
                                __half* __restrict__ oh)
{
    const int row = blockIdx.x, tid = threadIdx.x;
    const unsigned FULL = 0xffffffffu;
    float4 v = reinterpret_cast<const float4*>(x + (size_t)row*DM)[tid];
    float sq = fmaf(v.x,v.x, fmaf(v.y,v.y, fmaf(v.z,v.z, v.w*v.w)));
    float mx = fmaxf(fmaxf(v.x,v.y), fmaxf(v.z,v.w));
    __shared__ float rq[8], rm[8], rz[8];
    #pragma unroll
    for (int o=16;o;o>>=1){
        sq += __shfl_xor_sync(FULL,sq,o);
        mx  = fmaxf(mx, __shfl_xor_sync(FULL,mx,o));
    }
    int w = tid>>5, lane = tid&31;
    if (!lane){ rq[w]=sq; rm[w]=mx; }
    __syncthreads();
    float Q=0.f, MX=-3.4e38f;
    #pragma unroll
    for (int i=0;i<8;i++){ Q+=rq[i]; MX=fmaxf(MX,rm[i]); }
    const float it = 1.0f / fmaxf(taup[0], 1.0f);
    float4 g;
    g.x = expf((v.x-MX)*it); g.y = expf((v.y-MX)*it);
    g.z = expf((v.z-MX)*it); g.w = expf((v.w-MX)*it);
    float z = g.x+g.y+g.z+g.w;
    #pragma unroll
    for (int o=16;o;o>>=1) z += __shfl_xor_sync(FULL,z,o);
    if (!lane) rz[w]=z;
    __syncthreads();
    float Z=0.f;
    #pragma unroll
    for (int i=0;i<8;i++) Z += rz[i];
    const float rms = rsqrtf(Q*(1.0f/DM) + 1e-8f);
    const float c = rms * (float)DM / Z;
    float4 sc = reinterpret_cast<const float4*>(scale)[tid];
    float4 o4;
    o4.x = v.x*g.x*c*sc.x; o4.y = v.y*g.y*c*sc.y;
    o4.z = v.z*g.z*c*sc.z; o4.w = v.w*g.w*c*sc.w;
    if (out)
        reinterpret_cast<float4*>(out + (size_t)row*DM)[tid] = o4;
    uint2 hp;
    hp.x = pack_half2(o4.x, o4.y);
    hp.y = pack_half2(o4.z, o4.w);
    *reinterpret_cast<uint2*>(oh + (size_t)row*DM + tid*4) = hp;
}

// transpose: W [K,N] fp32 per expert -> out [e][N][K] fp16 (x64).
// If lo_out != nullptr, also writes the fp16 residual (2-term split).
__global__ void convT_kernel(const float* __restrict__ W,
                             __half* __restrict__ out,
                             __half* __restrict__ lo_out, int K, int N)
{
    __shared__ float t[32][33];
    int e = blockIdx.z;
    const float* Wp = W + (size_t)e*K*N;
    __half* hi = out + (size_t)e*(size_t)K*N;
    int k0 = blockIdx.x*32, n0 = blockIdx.y*32;
    int tx = threadIdx.x, ty = threadIdx.y;
    #pragma unroll
    for (int i=0;i<4;i++)
        t[ty+i*8][tx] = Wp[(size_t)(k0+ty+i*8)*N + n0+tx];
    __syncthreads();
    #pragma unroll
    for (int i=0;i<4;i++){
        float v = t[tx][ty+i*8] * WSCALE;
        __half h = __float2half_rn(v);
        size_t o = (size_t)(n0+ty+i*8)*K + k0+tx;
        hi[o] = h;
        if (lo_out)
            lo_out[(size_t)e*(size_t)K*N + o] = __float2half_rn(v - __half2float(h));
    }
}

// ---- parallel LRU scan, phase 1: per-chunk local scan (u fused from proj) --
__global__ void scan_local_kernel(const float* __restrict__ rec_w,
                                  const float* __restrict__ pos_bias)
{
    const int idx = blockIdx.x;            // (b, chunk): 0..127
    const int b = idx >> 5, c = idx & 31;
    const int d = threadIdx.x;             // 64 threads
    const float a = 1.0f / (1.0f + expf(-(rec_w[d] + pos_bias[d])));
    const size_t base = (size_t)b*TT + (size_t)c*64;
    float l = 0.f;
    #pragma unroll 8
    for (int t=0; t<64; t++){
        size_t row = base + t;
        float vin = tanhf(g_proj[row*2*DS + d]);
        float vg  = 1.0f / (1.0f + expf(-g_proj[row*2*DS + DS + d]));
        l = fmaf(a, l, vin*vg);
        g_states[row*DS + d] = l;
    }
    g_carry[idx*DS + d] = l;
}

// ---- phase 2: serial carry across chunks (32 steps, L2-resident) ----------
__global__ void scan_carry_kernel(const float* __restrict__ state,
                                  const float* __restrict__ rec_w,
                                  const float* __restrict__ pos_bias,
                                  float* __restrict__ out_state)
{
    const int tid = threadIdx.x;           // 256: (b,d)
    const int b = tid >> 6, d = tid & 63;
    const float a = 1.0f / (1.0f + expf(-(rec_w[d] + pos_bias[d])));
    float aC = a;
    #pragma unroll
    for (int i=0;i<6;i++) aC *= aC;        // a^64
    float h = state[tid];
    #pragma unroll
    for (int c=0; c<NCHK; c++){
        int o = (b*NCHK + c)*DS + d;
        g_hin[o] = h;
        h = fmaf(aC, h, g_carry[o]);
    }
    out_state[tid] = h;
}

// ---- phase 3: fixup locals with carry-in ----------------------------------
__global__ void scan_fix_kernel(const float* __restrict__ rec_w,
                                const float* __restrict__ pos_bias)
{
    const int idx = blockIdx.x;            // 0..127
    const int b = idx >> 5, c = idx & 31;
    const int d = threadIdx.x;
    const float a = 1.0f / (1.0f + expf(-(rec_w[d] + pos_bias[d])));
    const float hin = g_hin[idx*DS + d];
    const size_t base = ((size_t)b*TT + (size_t)c*64)*DS + d;
    float p = a;
    #pragma unroll 8
    for (int t=0; t<64; t++){
        g_states[base + (size_t)t*DS] = fmaf(p, hin, g_states[base + (size_t)t*DS]);
        p *= a;
    }
}

__global__ void router_kernel(const float* __restrict__ Wr,
                              const float* __restrict__ h2)
{
    int warp = threadIdx.x >> 5, lane = threadIdx.x & 31;
    int token = blockIdx.x*8 + warp;
    const unsigned FULL = 0xffffffffu;
    const float* xr = h2 + (size_t)token*DM;
    float acc[NE];
    #pragma unroll
    for (int e=0;e<NE;e++) acc[e]=0.f;
    for (int k=lane;k<DM;k+=32){
        float xv = xr[k];
        const float* wrow = Wr + k*NE;
        #pragma unroll
        for (int e=0;e<NE;e++) acc[e] = fmaf(xv, wrow[e], acc[e]);
    }
    #pragma unroll
    for (int o=16;o;o>>=1)
        #pragma unroll
        for (int e=0;e<NE;e++) acc[e] += __shfl_xor_sync(FULL, acc[e], o);

    __shared__ float sp[8][NE];
    if (lane==0){
        float mxv = acc[0];
        #pragma unroll
        for (int e=1;e<NE;e++) mxv = fmaxf(mxv, acc[e]);
        float p[NE]; float s=0.f;
        #pragma unroll
        for (int e=0;e<NE;e++){ p[e] = expf(acc[e]-mxv); s += p[e]; }
        float inv = 1.0f/s;
        #pragma unroll
        for (int e=0;e<NE;e++) p[e] *= inv;
        int i0=0; float p0=p[0];
        #pragma unroll
        for (int e=1;e<NE;e++) if (p[e] > p0){ p0=p[e]; i0=e; }
        int i1=-1; float p1=-1.f;
        #pragma unroll
        for (int e=0;e<NE;e++) if (e!=i0 && p[e] > p1){ p1=p[e]; i1=e; }
        float ws = 1.0f/(p0+p1);
        g_wtok[token*2+0] = p0*ws;
        g_wtok[token*2+1] = p1*ws;
        int pos0 = atomicAdd(&g_ecount[i0], 1);
        g_etok[i0*NT + pos0] = token;
        g_slot[token*2+0] = i0*NT + pos0;
        int pos1 = atomicAdd(&g_ecount[i1], 1);
        g_etok[i1*NT + pos1] = token;
        g_slot[token*2+1] = i1*NT + pos1;
        #pragma unroll
        for (int e=0;e<NE;e++) sp[warp][e] = p[e];
    }
    __syncthreads();
    if (threadIdx.x < NE){
        float s=0.f;
        #pragma unroll
        for (int w2=0;w2<8;w2++) s += sp[w2][threadIdx.x];
        g_partial[blockIdx.x*NE + threadIdx.x] = s;
    }
}

__global__ void aux_kernel(float* __restrict__ out)
{
    const unsigned FULL = 0xffffffffu;
    int e = threadIdx.x;
    float val = 0.f;
    if (e < NE){
        float s = 0.f;
        for (int b=0;b<NT/8;b++) s += g_partial[b*NE + e];
        float P = s / (float)NT;
        float f = (float)g_ecount[e] / (float)(NT*2);
        val = f * P;
    }
    #pragma unroll
    for (int o=16;o;o>>=1) val += __shfl_xor_sync(FULL, val, o);
    if (threadIdx.x==0) out[0] = (float)NE * val;
}

__global__ void combine_kernel(const float* __restrict__ x2,
                               float* __restrict__ out)
{
    int n = blockIdx.x, tid = threadIdx.x;
    int s0 = g_slot[n*2+0], s1 = g_slot[n*2+1];
    float w0 = g_wtok[n*2+0], w1 = g_wtok[n*2+1];
    float4 a = reinterpret_cast<const float4*>(x2 + (size_t)n*DM)[tid];
    uint2 pu = *reinterpret_cast<const uint2*>(g_obufh + (size_t)s0*DM + tid*4);
    uint2 qu = *reinterpret_cast<const uint2*>(g_obufh + (size_t)s1*DM + tid*4);
    float2 p0 = __half22float2(*reinterpret_cast<__half2*>(&pu.x));
    float2 p1 = __half22float2(*reinterpret_cast<__half2*>(&pu.y));
    float2 q0 = __half22float2(*reinterpret_cast<__half2*>(&qu.x));
    float2 q1 = __half22float2(*reinterpret_cast<__half2*>(&qu.y));
    a.x += fmaf(w1, q0.x, w0*p0.x);
    a.y += fmaf(w1, q0.y, w0*p0.y);
    a.z += fmaf(w1, q1.x, w0*p1.x);
    a.w += fmaf(w1, q1.y, w0*p1.y);
    reinterpret_cast<float4*>(out + (size_t)n*DM)[tid] = a;
}

// ---------------- fp32 SIMT GEMM (W_out only: K=64) -------------------------
template<int MODE>
__global__ void __launch_bounds__(256)
gemm128_kernel(const float* __restrict__ A, int lda,
               const float* __restrict__ Bm, int ldb,
               const float* __restrict__ bias,
               float* __restrict__ C, int ldc,
               int M, int K,
               const float* __restrict__ resid)
{
    const int m0 = blockIdx.y * 128;
    const int n0 = blockIdx.x * 128;

    __shared__ __align__(16) float As[8][128];
    __shared__ __align__(16) float Bs[8][128];

    const int tid = threadIdx.x;
    const int arow_l = tid >> 1;
    const int kpart  = (tid & 1) * 4;
    const int arow   = m0 + arow_l;
    const float* aptr = (arow < M) ? A + (size_t)arow*lda + kpart : A + kpart;

    const int bk = tid >> 5;
    const int bn = (tid & 31) * 4;
    const float* bptr = Bm + (size_t)bk*ldb + n0 + bn;

    const int ty = tid >> 4;
    const int tx = tid & 15;

    float acc[8][8];
    #pragma unroll
    for (int i=0;i<8;i++)
        #pragma unroll
        for (int j=0;j<8;j++) acc[i][j]=0.f;

    for (int k0=0; k0<K; k0+=8){
        float4 av = *reinterpret_cast<const float4*>(aptr + k0);
        float4 bv = *reinterpret_cast<const float4*>(bptr + (size_t)k0*ldb);
        As[kpart+0][arow_l] = av.x;
        As[kpart+1][arow_l] = av.y;
        As[kpart+2][arow_l] = av.z;
        As[kpart+3][arow_l] = av.w;
        *reinterpret_cast<float4*>(&Bs[bk][bn]) = bv;
        __syncthreads();
        #pragma unroll
        for (int k=0;k<8;k++){
            float4 a0 = *reinterpret_cast<const float4*>(&As[k][ty*8]);
            float4 a1 = *reinterpret_cast<const float4*>(&As[k][ty*8+4]);
            float4 b0 = *reinterpret_cast<const float4*>(&Bs[k][tx*8]);
            float4 b1 = *reinterpret_cast<const float4*>(&Bs[k][tx*8+4]);
            float am[8] = {a0.x,a0.y,a0.z,a0.w,a1.x,a1.y,a1.z,a1.w};
            float bb[8] = {b0.x,b0.y,b0.z,b0.w,b1.x,b1.y,b1.z,b1.w};
            #pragma unroll
            for (int i=0;i<8;i++)
                #pragma unroll
                for (int j=0;j<8;j++)
                    acc[i][j] = fmaf(am[i], bb[j], acc[i][j]);
        }
        __syncthreads();
    }

    #pragma unroll
    for (int i=0;i<8;i++){
        int r = m0 + ty*8 + i;
        if (r < M){
            float v[8];
            #pragma unroll
            for (int j=0;j<8;j++) v[j] = acc[i][j] + bias[n0 + tx*8 + j];
            if (MODE==2){
                const float4* rp = reinterpret_cast<const float4*>(
                    resid + (size_t)r*ldc + n0 + tx*8);
                float4 r0 = rp[0], r1 = rp[1];
                v[0]+=r0.x; v[1]+=r0.y; v[2]+=r0.z; v[3]+=r0.w;
                v[4]+=r1.x; v[5]+=r1.y; v[6]+=r1.z; v[7]+=r1.w;
            }
            float4* cp = reinterpret_cast<float4*>(C + (size_t)r*ldc + n0 + tx*8);
            cp[0] = make_float4(v[0],v[1],v[2],v[3]);
            cp[1] = make_float4(v[4],v[5],v[6],v[7]);
        }
    }
}

// ---------------- mma.sync fp16 GEMM (1- or 2-term B) -----------------------
// 4-stage cp.async pipeline, ONE __syncthreads per K-chunk, ldmatrix x4 frags.
// C[128,128] = (1/64)*( A@Bh^T [+ A@Bl^T] ) + bias   (B fp16 pre-scaled x64)
// MODE 0: fp32 out.  MODE 1: silu -> fp16 out.  MODE 2: plain fp16 out.
// GATHER: A rows via g_etok.  EXPERT: blockIdx.z = expert.
static constexpr int ROWB = 80;                    // 32 halves (64B) + 16 pad
static constexpr int TILEB = 128*ROWB;             // 10240
static constexpr int AOF = 0, BHo = TILEB, BLo = 2*TILEB;
static constexpr int NST = 4;                      // pipeline stages

template<int KSTRIDE, int BTERMS, int MODE, bool GATHER, bool EXPERT>
__global__ void __launch_bounds__(256,2)
mmagemm_kernel(const __half* __restrict__ Ain,
               const __half* __restrict__ Wt, int Ntot,
               const float* __restrict__ bias, int biasStride,
               float* __restrict__ Cf,
               __half* __restrict__ Ch,
               int ldc, int Min)
{
    constexpr int SB = (1 + BTERMS) * TILEB;       // per-stage smem bytes
    const int e = EXPERT ? blockIdx.z : 0;
    const int M = EXPERT ? g_ecount[e] : Min;
    const int m0 = blockIdx.y * 128;
    if (m0 >= M) return;
    const int n0 = blockIdx.x * 128;

    const __half* A = Ain;
    const __half* Bp = Wt + (EXPERT ? (size_t)e*(size_t)Ntot*KSTRIDE : (size_t)0);
    const __half* Bl = Bp + (size_t)Ntot*KSTRIDE;  // 2-term: lo plane follows hi

    extern __shared__ char sm[];
    __shared__ int   s_tok[128];
    __shared__ float s_bias[128];

    const int tid = threadIdx.x;
    const int lane = tid & 31, wid = tid >> 5;
    const int warp_m = wid & 3, warp_n = wid >> 2;   // 4 x 2 warps

    if (tid < 128){
        if (GATHER){
            int r = m0 + tid;
            s_tok[tid] = (r < M) ? g_etok[e*NT + r] : g_etok[e*NT];
        }
        s_bias[tid] = bias[(size_t)e*biasStride + n0 + tid];
    }
    __syncthreads();

    const size_t rowBase = (EXPERT ? (size_t)e*NT : (size_t)0) + m0;
    const uint32_t smb = smem_u32(sm);

    auto load_chunk = [&](int c, int s){
        const int k0 = c*32;
        const uint32_t st = smb + (uint32_t)s*SB;
        #pragma unroll
        for (int i = tid; i < 512; i += 256){
            int row = i >> 2, sg = i & 3;
            size_t ar = GATHER ? (size_t)s_tok[row] : (rowBase + row);
            size_t so = ar*(size_t)KSTRIDE + k0 + sg*8;
            uint32_t d = (uint32_t)(row*ROWB + sg*16);
            cp16(st + AOF + d, A + so);
        }
        #pragma unroll
        for (int i = tid; i < 512; i += 256){
            int row = i >> 2, sg = i & 3;
            size_t so = (size_t)(n0+row)*KSTRIDE + k0 + sg*8;
            uint32_t d = (uint32_t)(row*ROWB + sg*16);
            cp16(st + BHo + d, Bp + so);
            if (BTERMS == 2)
                cp16(st + BLo + d, Bl + so);
        }
        cp_commit();
    };

    float acc[2][8][4];
    #pragma unroll
    for (int i=0;i<2;i++)
        #pragma unroll
        for (int j=0;j<8;j++)
            #pragma unroll
            for (int q=0;q<4;q++) acc[i][j][q]=0.f;

    const int NCH = KSTRIDE/32;                    // >= 32 always
    load_chunk(0,0);
    load_chunk(1,1);
    load_chunk(2,2);

    // ldmatrix per-thread selectors
    const int rA = lane & 15;                      // A: rows 0-15 of the 16x16 frag
    const uint32_t cA = (uint32_t)(lane >> 4) * 16;// lanes>=16: k+8 (16B)
    // B x4: matrix id = lane>>3: m0=(nt,k0) m1=(nt,k8) m2=(nt+1,k0) m3=(nt+1,k8)
    const int rB = lane & 7;
    const uint32_t nB = (uint32_t)((lane >> 4) & 1) * 8;   // +8 n-rows for m2/m3
    const uint32_t cB = (uint32_t)((lane >> 3) & 1) * 16;  // k8 half for m1/m3

    for (int c = 0; c < NCH; c++){
        const int rem = NCH - 1 - c;               // loads issued after chunk c
        if (rem >= 2)      cp_wait<2>();
        else if (rem == 1) cp_wait<1>();
        else               cp_wait<0>();
        __syncthreads();                           // single barrier per chunk
        const uint32_t S = smb + (uint32_t)(c & 3)*SB;

        #pragma unroll
        for (int ks = 0; ks < 2; ks++){
            const uint32_t kbase = (uint32_t)ks*32;
            uint32_t ah[2][4];
            #pragma unroll
            for (int mt=0; mt<2; mt++){
                uint32_t addr = S + AOF
                    + (uint32_t)((warp_m*32 + mt*16 + rA)*ROWB) + kbase + cA;
                ldsm_x4(ah[mt], addr);
            }
            #pragma unroll
            for (int nt=0; nt<8; nt+=2){
                const uint32_t nrow =
                    (uint32_t)((warp_n*64 + nt*8 + nB + rB)*ROWB);
                uint32_t bb[4];
                ldsm_x4(bb, S + BHo + nrow + kbase + cB);
                #pragma unroll
                for (int mt=0; mt<2; mt++){
                    mma16816(acc[mt][nt],   ah[mt], &bb[0]);
                    mma16816(acc[mt][nt+1], ah[mt], &bb[2]);
                }
                if (BTERMS == 2){
                    uint32_t bl[4];
                    ldsm_x4(bl, S + BLo + nrow + kbase + cB);
                    #pragma unroll
                    for (int mt=0; mt<2; mt++){
                        mma16816(acc[mt][nt],   ah[mt], &bl[0]);
                        mma16816(acc[mt][nt+1], ah[mt], &bl[2]);
                    }
                }
            }
        }
        // load 3 ahead into stage (c+3)&3 — its last readers ran chunk c-1,
        // which every warp finished before this chunk's barrier.
        if (c+3 < NCH) load_chunk(c+3, (c+3) & 3);
    }

    // ---- epilogue ----
    const int colb = warp_n*64 + (lane&3)*2;
    #pragma unroll
    for (int mt=0; mt<2; mt++){
        int rl = m0 + warp_m*32 + mt*16 + (lane>>2);   // rows rl, rl+8
        #pragma unroll
        for (int nt=0; nt<8; nt++){
            int ncol = colb + nt*8;
            float b0 = s_bias[ncol], b1 = s_bias[ncol+1];
            float v0 = fmaf(acc[mt][nt][0], WINV, b0);
            float v1 = fmaf(acc[mt][nt][1], WINV, b1);
            float v2 = fmaf(acc[mt][nt][2], WINV, b0);
            float v3 = fmaf(acc[mt][nt][3], WINV, b1);
            if (MODE != 0){
                if (MODE == 1){
                    v0 = v0/(1.0f+expf(-v0)); v1 = v1/(1.0f+expf(-v1));
                    v2 = v2/(1.0f+expf(-v2)); v3 = v3/(1.0f+expf(-v3));
                }
                if (rl < M){
                    size_t off = (rowBase - m0 + rl)*(size_t)ldc + n0 + ncol;
                    *reinterpret_cast<uint32_t*>(Ch + off) = pack_half2(v0, v1);
                }
                if (rl + 8 < M){
                    size_t off = (rowBase - m0 + rl + 8)*(size_t)ldc + n0 + ncol;
                    *reinterpret_cast<uint32_t*>(Ch + off) = pack_half2(v2, v3);
                }
            } else {
                if (rl < M){
                    size_t off = (rowBase - m0 + rl)*(size_t)ldc + n0 + ncol;
                    *reinterpret_cast<float2*>(Cf + off) = make_float2(v0, v1);
                }
                if (rl + 8 < M){
                    size_t off = (rowBase - m0 + rl + 8)*(size_t)ldc + n0 + ncol;
                    *reinterpret_cast<float2*>(Cf + off) = make_float2(v2, v3);
                }
            }
        }
    }
}

static constexpr int MM_DYN1 = NST*2*TILEB;        // 1-term: 81920
static constexpr int MM_DYN2 = NST*3*TILEB;        // 2-term: 122880

// ---------------- launch ----------------------------------------------------
extern "C" void kernel_launch(void* const* d_in, const int* in_sizes, int n_in,
                              void* d_out, int out_size)
{
    const float* x      = (const float*)d_in[0];
    const float* state  = (const float*)d_in[1];
    const float* tau1   = (const float*)d_in[2];
    const float* scale1 = (const float*)d_in[3];
    const float* tau2   = (const float*)d_in[4];
    const float* scale2 = (const float*)d_in[5];
    const float* W_in   = (const float*)d_in[6];
    const float* b_in   = (const float*)d_in[7];
    const float* rec_w  = (const float*)d_in[8];
    const float* pos_b  = (const float*)d_in[9];
    const float* W_out  = (const float*)d_in[10];
    const float* b_out  = (const float*)d_in[11];
    const float* W_r    = (const float*)d_in[12];
    const float* We1    = (const float*)d_in[13];
    const float* be1    = (const float*)d_in[14];
    const float* We2    = (const float*)d_in[15];
    const float* be2    = (const float*)d_in[16];
    float* out = (float*)d_out;
    float* out_state = out + (size_t)NT*DM;
    float* out_aux   = out_state + NB*DS;

    float *p_proj, *p_states, *p_x2, *p_h2;
    __half *p_h1h, *p_h2h, *p_wint, *p_w1t, *p_w2t, *p_hidf, *p_obufh;
    cudaGetSymbolAddress((void**)&p_h1h,   g_h1h);
    cudaGetSymbolAddress((void**)&p_proj,  g_proj);
    cudaGetSymbolAddress((void**)&p_states,g_states);
    cudaGetSymbolAddress((void**)&p_x2,    g_x2);
    cudaGetSymbolAddress((void**)&p_h2,    g_h2);
    cudaGetSymbolAddress((void**)&p_h2h,   g_h2h);
    cudaGetSymbolAddress((void**)&p_wint,  g_wint);
    cudaGetSymbolAddress((void**)&p_w1t,   g_w1t);
    cudaGetSymbolAddress((void**)&p_w2t,   g_w2t);
    cudaGetSymbolAddress((void**)&p_hidf,  g_hidf);
    cudaGetSymbolAddress((void**)&p_obufh, g_obufh);

    cudaFuncSetAttribute(mmagemm_kernel<DM, 2, 0, false, false>,
                         cudaFuncAttributeMaxDynamicSharedMemorySize, MM_DYN2);
    cudaFuncSetAttribute(mmagemm_kernel<DM, 1, 1, true, true>,
                         cudaFuncAttributeMaxDynamicSharedMemorySize, MM_DYN1);
    cudaFuncSetAttribute(mmagemm_kernel<FF, 1, 2, false, true>,
                         cudaFuncAttributeMaxDynamicSharedMemorySize, MM_DYN1);

    // side stream + events for weight-prep overlap (created once, uncaptured run)
    static cudaStream_t s2 = nullptr;
    static cudaEvent_t evFork = nullptr, evJoin = nullptr;
    if (!s2){
        cudaStreamCreateWithFlags(&s2, cudaStreamNonBlocking);
        cudaEventCreateWithFlags(&evFork, cudaEventDisableTiming);
        cudaEventCreateWithFlags(&evJoin, cudaEventDisableTiming);
    }

    reset_kernel<<<1,32>>>();

    // fork: expert weight transposes run concurrently with the LRU chain
    cudaEventRecord(evFork, 0);
    cudaStreamWaitEvent(s2, evFork, 0);
    convT_kernel<<<dim3(DM/32, FF/32, NE), dim3(32,8), 0, s2>>>(We1, p_w1t, nullptr, DM, FF);
    convT_kernel<<<dim3(FF/32, DM/32, NE), dim3(32,8), 0, s2>>>(We2, p_w2t, nullptr, FF, DM);
    cudaEventRecord(evJoin, s2);

    // main chain: W_in transpose (needed by proj) stays here
    convT_kernel<<<dim3(DM/32, 128/32, 1), dim3(32,8)>>>(
        W_in, p_wint, p_wint + (size_t)128*DM, DM, 128);

    // 1. compnorm1 (fp16 only)
    compnorm_kernel<<<NT,256>>>(x, tau1, scale1, nullptr, p_h1h);

    // 2. proj = h1 @ W_in + b_in  (mma, N=128, 2-term B: router-path accuracy)
    mmagemm_kernel<DM, 2, 0, false, false><<<dim3(1, NT/128), 256, MM_DYN2>>>(
        p_h1h, p_wint, 128, b_in, 0, p_proj, nullptr, 128, NT);

    // 3-4. parallel LRU scan (u fused from proj)
    scan_local_kernel<<<NB*NCHK, 64>>>(rec_w, pos_b);
    scan_carry_kernel<<<1, 256>>>(state, rec_w, pos_b, out_state);
    scan_fix_kernel<<<NB*NCHK, 64>>>(rec_w, pos_b);

    // 5. x2 = x + states @ W_out + b_out  (SIMT fp32, K=64)
    gemm128_kernel<2><<<dim3(DM/128, NT/128), 256>>>(
        p_states, DS, W_out, DM, b_out, p_x2, DM, NT, DS, x);

    // 6. compnorm2 (fp32 for router + fp16 for mma)
    compnorm_kernel<<<NT,256>>>(p_x2, tau2, scale2, p_h2, p_h2h);

    // 7. router + dispatch
    router_kernel<<<NT/8, 256>>>(W_r, p_h2);

    // 8. aux loss
    aux_kernel<<<1,32>>>(out_aux);

    // join: expert weights must be ready before GEMM1
    cudaStreamWaitEvent(0, evJoin, 0);

    // 9. expert GEMM1: hidden = silu(gather(h2) @ We1[e] + be1[e]) -> fp16
    mmagemm_kernel<DM, 1, 1, true, true><<<dim3(FF/128, NT/128, NE), 256, MM_DYN1>>>(
        p_h2h, p_w1t, FF, be1, FF, nullptr, p_hidf, FF, 0);

    // 10. expert GEMM2: obuf = hidden @ We2[e] + be2[e] -> fp16
    mmagemm_kernel<FF, 1, 2, false, true><<<dim3(DM/128, NT/128, NE), 256, MM_DYN1>>>(
        p_hidf, p_w2t, DM, be2, DM, nullptr, p_obufh, DM, 0);

    // 11. combine into d_out
    combine_kernel<<<NT,256>>>(p_x2, out);
}